// round 5
// baseline (speedup 1.0000x reference)
#include <cuda_runtime.h>
#include <cuda_fp16.h>
#include <cstdint>

// Problem shape (fixed): B=4, S=1024 -> M=4096 rows; K=4096; N=4096.
#define M_DIM 4096
#define N_DIM 4096
#define K_DIM 4096
#define BK 64
#define KT (K_DIM / BK)   // 64 k-tiles

// fp16 scratch (device globals: allocation-free scratch per harness rules)
__device__ __align__(1024) __half g_Xh[(size_t)M_DIM * K_DIM];
__device__ __align__(1024) __half g_Wh[(size_t)N_DIM * K_DIM];

// ---------------------------------------------------------------------------
// Conversion kernels
// ---------------------------------------------------------------------------
__global__ void conv_x_kernel(const float* __restrict__ x, int n4) {
    int i  = blockIdx.x * blockDim.x + threadIdx.x;
    int st = gridDim.x * blockDim.x;
    const float4* x4 = (const float4*)x;
    uint2* o = (uint2*)g_Xh;
    for (; i < n4; i += st) {
        float4 v = x4[i];
        __half2 a = __floats2half2_rn(v.x, v.y);
        __half2 b = __floats2half2_rn(v.z, v.w);
        uint2 u;
        u.x = *reinterpret_cast<unsigned*>(&a);
        u.y = *reinterpret_cast<unsigned*>(&b);
        o[i] = u;
    }
}

__global__ void conv_w_kernel(const int* __restrict__ q, const int* __restrict__ zp, int n4) {
    int i  = blockIdx.x * blockDim.x + threadIdx.x;
    int st = gridDim.x * blockDim.x;
    const int4* q4 = (const int4*)q;
    uint2* o = (uint2*)g_Wh;
    for (; i < n4; i += st) {
        int4 v = q4[i];
        int n = i >> 10;              // (4*i) >> 12, K=4096
        int z = __ldg(zp + n);
        __half2 a = __halves2half2(__int2half_rn(v.x - z), __int2half_rn(v.y - z));
        __half2 b = __halves2half2(__int2half_rn(v.z - z), __int2half_rn(v.w - z));
        uint2 u;
        u.x = *reinterpret_cast<unsigned*>(&a);
        u.y = *reinterpret_cast<unsigned*>(&b);
        o[i] = u;
    }
}

// ---------------------------------------------------------------------------
// GEMM helpers (baseline-PTX tensor core path: ldmatrix + mma.sync)
// ---------------------------------------------------------------------------
__device__ __forceinline__ uint32_t cvta_smem(const void* p) {
    uint32_t a;
    asm("{ .reg .u64 t; cvta.to.shared.u64 t, %1; cvt.u32.u64 %0, t; }" : "=r"(a) : "l"(p));
    return a;
}

__device__ __forceinline__ void cp16(uint32_t d, const void* s) {
    asm volatile("cp.async.cg.shared.global [%0], [%1], 16;" :: "r"(d), "l"(s));
}
__device__ __forceinline__ void cp_commit() { asm volatile("cp.async.commit_group;" ::: "memory"); }
__device__ __forceinline__ void cp_wait1()  { asm volatile("cp.async.wait_group 1;" ::: "memory"); }
__device__ __forceinline__ void cp_wait0()  { asm volatile("cp.async.wait_group 0;" ::: "memory"); }

__device__ __forceinline__ void ldsm_x4(uint32_t* r, uint32_t addr) {
    asm volatile("ldmatrix.sync.aligned.m8n8.x4.shared.b16 {%0,%1,%2,%3}, [%4];"
        : "=r"(r[0]), "=r"(r[1]), "=r"(r[2]), "=r"(r[3]) : "r"(addr));
}

__device__ __forceinline__ void mma16816(float* c, const uint32_t* a, uint32_t b0, uint32_t b1) {
    asm volatile(
        "mma.sync.aligned.m16n8k16.row.col.f32.f16.f16.f32 "
        "{%0,%1,%2,%3}, {%4,%5,%6,%7}, {%8,%9}, {%0,%1,%2,%3};"
        : "+f"(c[0]), "+f"(c[1]), "+f"(c[2]), "+f"(c[3])
        : "r"(a[0]), "r"(a[1]), "r"(a[2]), "r"(a[3]), "r"(b0), "r"(b1));
}

// SMEM layout:
//   [0, 16K)      stage0 A tile  (128 rows x 64 half, SW128-swizzled, 128B rows)
//   [16K, 32K)    stage0 B tile
//   [32K, 48K)    stage1 A tile
//   [48K, 64K)    stage1 B tile
//   [65536)       s_scale[128] f32
//   [66048)       s_bias[128]  f32
#define OFF_SC   65536
#define OFF_BI   66048
#define SMEM_BYTES 66560

__global__ void __launch_bounds__(256, 2) gemm_kernel(
    const float* __restrict__ scales,
    const float* __restrict__ bias,
    float* __restrict__ out
) {
    extern __shared__ __align__(1024) char sm[];
    uint32_t SB = cvta_smem(sm);

    int tid  = threadIdx.x;
    int lane = tid & 31;
    int wid  = tid >> 5;
    int warp_m = wid >> 2;   // 0..1  (64 rows each)
    int warp_n = wid & 3;    // 0..3  (32 cols each)
    int bx = blockIdx.x;     // N tile
    int by = blockIdx.y;     // M tile

    float* s_scale = (float*)(sm + OFF_SC);
    float* s_bias  = (float*)(sm + OFF_BI);
    if (tid < 128) {
        s_scale[tid] = scales[bx * 128 + tid];
        s_bias[tid]  = bias[bx * 128 + tid];
    }

    // ---- global->shared loader geometry (per thread: 4 chunks of 16B per tile)
    int lrow = tid >> 3;           // 0..31 (+32*i)
    int lcb  = (tid & 7) * 16;     // byte column within 128B row
    const __half* gA = g_Xh + ((size_t)by * 128 + lrow) * K_DIM + (tid & 7) * 8;
    const __half* gB = g_Wh + ((size_t)bx * 128 + lrow) * K_DIM + (tid & 7) * 8;

    // ---- fragment-load geometry
    // A (16x16 tile): lane -> row (lane&15), k-chunk (lane>>4)
    int a_r  = lane & 15;
    int a_cb = (lane >> 4) * 16;   // byte offset within k16 (two 16B chunks)
    uint32_t aoff[4], axr[4];
#pragma unroll
    for (int mi = 0; mi < 4; mi++) {
        int row = warp_m * 64 + mi * 16 + a_r;
        aoff[mi] = (uint32_t)(row * 128);
        axr[mi]  = (uint32_t)((row & 7) << 4);
    }
    // B (k16 x n16 tile): lane -> n = ((lane>>4)<<3)+(lane&7), k-chunk ((lane>>3)&1)
    int b_n  = ((lane >> 4) << 3) + (lane & 7);
    int b_cb = ((lane >> 3) & 1) * 16;
    uint32_t boff[2], bxr[2];
#pragma unroll
    for (int nt = 0; nt < 2; nt++) {
        int n = warp_n * 32 + nt * 16 + b_n;
        boff[nt] = (uint32_t)(n * 128);
        bxr[nt]  = (uint32_t)((n & 7) << 4);
    }

    float acc[4][4][4];
#pragma unroll
    for (int mi = 0; mi < 4; mi++)
#pragma unroll
        for (int nj = 0; nj < 4; nj++)
#pragma unroll
            for (int c = 0; c < 4; c++) acc[mi][nj][c] = 0.0f;

    // ---- prologue: stage 0
    {
        uint32_t sA = SB, sBuf = SB + 16384;
#pragma unroll
        for (int i = 0; i < 4; i++) {
            int row = lrow + 32 * i;
            uint32_t sw = (uint32_t)(row * 128) + ((uint32_t)lcb ^ (uint32_t)((row & 7) << 4));
            cp16(sA   + sw, gA + (size_t)(32 * i) * K_DIM);
            cp16(sBuf + sw, gB + (size_t)(32 * i) * K_DIM);
        }
        cp_commit();
    }

    for (int kt = 0; kt < KT; kt++) {
        int cur = kt & 1;
        if (kt + 1 < KT) {
            uint32_t sA = SB + (uint32_t)((kt + 1) & 1) * 32768u;
            uint32_t sBuf = sA + 16384u;
            const __half* pa = gA + (size_t)(kt + 1) * BK;
            const __half* pb = gB + (size_t)(kt + 1) * BK;
#pragma unroll
            for (int i = 0; i < 4; i++) {
                int row = lrow + 32 * i;
                uint32_t sw = (uint32_t)(row * 128) + ((uint32_t)lcb ^ (uint32_t)((row & 7) << 4));
                cp16(sA   + sw, pa + (size_t)(32 * i) * K_DIM);
                cp16(sBuf + sw, pb + (size_t)(32 * i) * K_DIM);
            }
            cp_commit();
            cp_wait1();
        } else {
            cp_wait0();
        }
        __syncthreads();

        uint32_t SA = SB + (uint32_t)cur * 32768u;
        uint32_t SW = SA + 16384u;

#pragma unroll
        for (int ks = 0; ks < 4; ks++) {
            uint32_t a[4][4];
#pragma unroll
            for (int mi = 0; mi < 4; mi++)
                ldsm_x4(a[mi], SA + aoff[mi] + (((uint32_t)(ks * 32 + a_cb)) ^ axr[mi]));
            uint32_t b[2][4];
#pragma unroll
            for (int nt = 0; nt < 2; nt++)
                ldsm_x4(b[nt], SW + boff[nt] + (((uint32_t)(ks * 32 + b_cb)) ^ bxr[nt]));
#pragma unroll
            for (int mi = 0; mi < 4; mi++)
#pragma unroll
                for (int nj = 0; nj < 4; nj++)
                    mma16816(acc[mi][nj], a[mi], b[nj >> 1][(nj & 1) * 2], b[nj >> 1][(nj & 1) * 2 + 1]);
        }
        __syncthreads();   // protect 'cur' buffers from next iteration's cp.async
    }

    // ---- epilogue: scale/bias + store
    int g    = lane >> 2;         // 0..7
    int col2 = (lane & 3) * 2;    // 0,2,4,6
#pragma unroll
    for (int mi = 0; mi < 4; mi++) {
#pragma unroll
        for (int nj = 0; nj < 4; nj++) {
            int nloc = warp_n * 32 + nj * 8 + col2;
            float sc0 = s_scale[nloc], sc1 = s_scale[nloc + 1];
            float bi0 = s_bias[nloc],  bi1 = s_bias[nloc + 1];
            int m0 = warp_m * 64 + mi * 16 + g;
            size_t base0 = ((size_t)by * 128 + m0) * N_DIM + (size_t)bx * 128 + nloc;
            size_t base1 = base0 + 8 * (size_t)N_DIM;
            float2 v0, v1;
            v0.x = acc[mi][nj][0] * sc0 + bi0;
            v0.y = acc[mi][nj][1] * sc1 + bi1;
            v1.x = acc[mi][nj][2] * sc0 + bi0;
            v1.y = acc[mi][nj][3] * sc1 + bi1;
            *reinterpret_cast<float2*>(out + base0) = v0;
            *reinterpret_cast<float2*>(out + base1) = v1;
        }
    }
}

// ---------------------------------------------------------------------------
extern "C" void kernel_launch(void* const* d_in, const int* in_sizes, int n_in,
                              void* d_out, int out_size) {
    const float* x      = (const float*)d_in[0];
    const int*   qw     = (const int*)d_in[1];
    const float* scales = (const float*)d_in[2];
    const int*   zp     = (const int*)d_in[3];
    const float* bias   = (const float*)d_in[4];
    float* out = (float*)d_out;

    const int n4x = (int)(((size_t)M_DIM * K_DIM) / 4);
    const int n4w = (int)(((size_t)N_DIM * K_DIM) / 4);

    conv_x_kernel<<<2048, 256>>>(x, n4x);
    conv_w_kernel<<<2048, 256>>>(qw, zp, n4w);

    cudaFuncSetAttribute(gemm_kernel, cudaFuncAttributeMaxDynamicSharedMemorySize, SMEM_BYTES);
    dim3 grid(N_DIM / 128, M_DIM / 128);
    gemm_kernel<<<grid, 256, SMEM_BYTES>>>(scales, bias, out);
}